// round 10
// baseline (speedup 1.0000x reference)
#include <cuda_runtime.h>
#include <math.h>

#define BB     2
#define SS     2048
#define DMODEL 1024
#define HQ     32
#define HKV    8
#define HD     32

// ---------------- scratch (no allocs allowed) ----------------
__device__ float g_q [BB*HQ *SS*HD];   // [b][h][s][d]
__device__ float g_k [BB*HKV*SS*HD];
__device__ float g_v [BB*HKV*SS*HD];
__device__ float g_ao[BB*SS*DMODEL];   // attention out, [b][s][h*HD+d]

// packed fp32x2 helpers (sm_100+ PTX; 2 MACs per issue slot)
#define FMA2(d, a, b) \
    asm("fma.rn.f32x2 %0, %1, %2, %0;" : "+l"(d) : "l"(a), "l"(b))
#define MUL2(d, c) \
    asm("mul.rn.f32x2 %0, %0, %1;" : "+l"(d) : "l"(c))
#define DUP2(d, f) \
    asm("mov.b64 %0, {%1, %1};" : "=l"(d) : "f"(f))

// ---------------- GEMM config ----------------
#define GBM 128
#define GBN 128
#define GBK 16
#define NT  (DMODEL / GBK)

// A tile stored DUPLICATED (each value twice) so LDS.128 yields 2 ready f32x2
// a-operands; B pairs are naturally contiguous.
#define STASH(bf)                                                              \
    do {                                                                       \
        *(float2*)&As2[bf][lc+0][2*lrow]      = make_float2(ra0.x, ra0.x);     \
        *(float2*)&As2[bf][lc+1][2*lrow]      = make_float2(ra0.y, ra0.y);     \
        *(float2*)&As2[bf][lc+2][2*lrow]      = make_float2(ra0.z, ra0.z);     \
        *(float2*)&As2[bf][lc+3][2*lrow]      = make_float2(ra0.w, ra0.w);     \
        *(float2*)&As2[bf][lc+0][2*(lrow+64)] = make_float2(ra1.x, ra1.x);     \
        *(float2*)&As2[bf][lc+1][2*(lrow+64)] = make_float2(ra1.y, ra1.y);     \
        *(float2*)&As2[bf][lc+2][2*(lrow+64)] = make_float2(ra1.z, ra1.z);     \
        *(float2*)&As2[bf][lc+3][2*(lrow+64)] = make_float2(ra1.w, ra1.w);     \
        Bs[bf][lc+0][lrow]    = rb0.x; Bs[bf][lc+1][lrow]    = rb0.y;          \
        Bs[bf][lc+2][lrow]    = rb0.z; Bs[bf][lc+3][lrow]    = rb0.w;          \
        Bs[bf][lc+0][lrow+64] = rb1.x; Bs[bf][lc+1][lrow+64] = rb1.y;          \
        Bs[bf][lc+2][lrow+64] = rb1.z; Bs[bf][lc+3][lrow+64] = rb1.w;          \
    } while (0)

#define GEMM_MAINLOOP()                                                        \
    float4 ra0 = *(const float4*)pa0;                                          \
    float4 ra1 = *(const float4*)pa1;                                          \
    float4 rb0 = *(const float4*)pb0;                                          \
    float4 rb1 = *(const float4*)pb1;                                          \
    STASH(0);                                                                  \
    __syncthreads();                                                           \
    int buf = 0;                                                               \
    for (int t = 0; t < NT; t++) {                                             \
        if (t + 1 < NT) {                                                      \
            pa0 += GBK; pa1 += GBK; pb0 += GBK; pb1 += GBK;                    \
            ra0 = *(const float4*)pa0; ra1 = *(const float4*)pa1;              \
            rb0 = *(const float4*)pb0; rb1 = *(const float4*)pb1;              \
        }                                                                      \
        _Pragma("unroll")                                                      \
        for (int k = 0; k < GBK; k++) {                                        \
            const ulonglong2* ap = (const ulonglong2*)&As2[buf][k][ty * 16];   \
            const ulonglong2* bp = (const ulonglong2*)&Bs[buf][k][tx * 8];     \
            ulonglong2 A0 = ap[0], A1 = ap[1], A2 = ap[2], A3 = ap[3];         \
            ulonglong2 B0 = bp[0], B1 = bp[1];                                 \
            unsigned long long av[8] = {A0.x,A0.y,A1.x,A1.y,A2.x,A2.y,A3.x,A3.y}; \
            unsigned long long bv[4] = {B0.x,B0.y,B1.x,B1.y};                  \
            _Pragma("unroll")                                                  \
            for (int i = 0; i < 8; i++) {                                      \
                FMA2(acc2[i][0], av[i], bv[0]);                                \
                FMA2(acc2[i][1], av[i], bv[1]);                                \
                FMA2(acc2[i][2], av[i], bv[2]);                                \
                FMA2(acc2[i][3], av[i], bv[3]);                                \
            }                                                                  \
        }                                                                      \
        if (t + 1 < NT) {                                                      \
            STASH(buf ^ 1);                                                    \
            __syncthreads();                                                   \
            buf ^= 1;                                                          \
        }                                                                      \
    }

// fused Q/K/V projection with scatter epilogue
__global__ __launch_bounds__(256, 2) void gemm_qkv(
    const float* __restrict__ A,
    const float* __restrict__ Wq,
    const float* __restrict__ Wk,
    const float* __restrict__ Wv)
{
    __shared__ __align__(16) float As2[2][GBK][2 * GBM];  // duplicated A
    __shared__ __align__(16) float Bs [2][GBK][GBN];

    const int m0 = blockIdx.y * GBM;
    const int n0 = blockIdx.x * GBN;

    const float* W; int wn0; float* dst; int H;
    if (n0 < 1024)      { W = Wq; wn0 = n0;        dst = g_q; H = HQ;  }
    else if (n0 < 1280) { W = Wk; wn0 = n0 - 1024; dst = g_k; H = HKV; }
    else                { W = Wv; wn0 = n0 - 1280; dst = g_v; H = HKV; }

    const int tid  = threadIdx.x;
    const int tx   = tid & 15;
    const int ty   = tid >> 4;
    const int lrow = tid >> 2;
    const int lc   = (tid & 3) * 4;

    const float* pa0 = A + (m0 + lrow)      * DMODEL + lc;
    const float* pa1 = A + (m0 + lrow + 64) * DMODEL + lc;
    const float* pb0 = W + (wn0 + lrow)      * DMODEL + lc;
    const float* pb1 = W + (wn0 + lrow + 64) * DMODEL + lc;

    unsigned long long acc2[8][4];
    #pragma unroll
    for (int i = 0; i < 8; i++)
        #pragma unroll
        for (int j = 0; j < 4; j++) acc2[i][j] = 0ull;

    GEMM_MAINLOOP();

    #pragma unroll
    for (int i = 0; i < 8; i++) {
        int m = m0 + ty * 8 + i;
        int b = m >> 11;
        int s = m & (SS - 1);
        #pragma unroll
        for (int jp = 0; jp < 4; jp++) {
            int nl = wn0 + tx * 8 + 2 * jp;
            int h  = nl >> 5;
            int d  = nl & 31;       // d even, d+1 in same head
            *(float2*)&dst[((b * H + h) * SS + s) * HD + d] = *(float2*)&acc2[i][jp];
        }
    }
}

// output projection: C = g_ao @ Wo^T
__global__ __launch_bounds__(256, 2) void gemm_out(
    const float* __restrict__ W, float* __restrict__ C)
{
    __shared__ __align__(16) float As2[2][GBK][2 * GBM];
    __shared__ __align__(16) float Bs [2][GBK][GBN];

    const int m0 = blockIdx.y * GBM;
    const int n0 = blockIdx.x * GBN;

    const int tid  = threadIdx.x;
    const int tx   = tid & 15;
    const int ty   = tid >> 4;
    const int lrow = tid >> 2;
    const int lc   = (tid & 3) * 4;

    const float* pa0 = g_ao + (m0 + lrow)      * DMODEL + lc;
    const float* pa1 = g_ao + (m0 + lrow + 64) * DMODEL + lc;
    const float* pb0 = W + (n0 + lrow)      * DMODEL + lc;
    const float* pb1 = W + (n0 + lrow + 64) * DMODEL + lc;

    unsigned long long acc2[8][4];
    #pragma unroll
    for (int i = 0; i < 8; i++)
        #pragma unroll
        for (int j = 0; j < 4; j++) acc2[i][j] = 0ull;

    GEMM_MAINLOOP();

    #pragma unroll
    for (int i = 0; i < 8; i++) {
        int m = m0 + ty * 8 + i;
        #pragma unroll
        for (int jp = 0; jp < 4; jp++)
            *(float2*)&C[m * DMODEL + n0 + tx * 8 + 2 * jp] = *(float2*)&acc2[i][jp];
    }
}

// ---------------- RoPE over g_q and g_k ----------------
__global__ void rope_kernel() {
    const int NQROWS = BB * HQ * SS;
    const int TOT    = (NQROWS + BB * HKV * SS) * 16;
    int gid = blockIdx.x * blockDim.x + threadIdx.x;
    if (gid >= TOT) return;
    int row = gid >> 4;
    int i   = gid & 15;
    float* base = (row < NQROWS) ? (g_q + row * HD)
                                 : (g_k + (row - NQROWS) * HD);
    int s = row & (SS - 1);
    float inv_freq = expf(-(float)i * (9.210340371976184f / 16.0f));
    float ang = (float)s * inv_freq;
    float c, sn;
    sincosf(ang, &sn, &c);
    float x1 = base[i];
    float x2 = base[i + 16];
    base[i]      = x1 * c - x2 * sn;
    base[i + 16] = x2 * c + x1 * sn;
}

// ---------------- causal GQA flash attention ----------------
// one thread = one query row for TWO adjacent Q heads (same KV head).
// All dot products / accumulations in packed f32x2 (2 MACs per issue).
__global__ __launch_bounds__(128, 1) void attention_kernel(const int* __restrict__ mask) {
    const int b   = blockIdx.z;
    const int h0  = blockIdx.y * 2;          // heads h0, h0+1 share kv head
    const int q0  = blockIdx.x * 128;
    const int tid = threadIdx.x;
    const int r   = q0 + tid;
    const int kvh = h0 >> 2;                 // GROUP = 4
    const float scale = 0.17677669529663687f; // 1/sqrt(32)

    __shared__ float4 Ks[64][8];
    __shared__ float4 Vs[64][8];
    __shared__ int smask[64];

    const float* qp0 = g_q + ((b * HQ + h0    ) * SS + r) * HD;
    const float* qp1 = g_q + ((b * HQ + h0 + 1) * SS + r) * HD;
    unsigned long long qa2[16], qb2[16];
    #pragma unroll
    for (int c = 0; c < 8; c++) {
        float4 t0 = ((const float4*)qp0)[c];
        t0.x *= scale; t0.y *= scale; t0.z *= scale; t0.w *= scale;
        ulonglong2 u0 = *(ulonglong2*)&t0;
        qa2[2*c] = u0.x; qa2[2*c+1] = u0.y;
        float4 t1 = ((const float4*)qp1)[c];
        t1.x *= scale; t1.y *= scale; t1.z *= scale; t1.w *= scale;
        ulonglong2 u1 = *(ulonglong2*)&t1;
        qb2[2*c] = u1.x; qb2[2*c+1] = u1.y;
    }

    const float* kbase = g_k + (b * HKV + kvh) * SS * HD;
    const float* vbase = g_v + (b * HKV + kvh) * SS * HD;
    const int*   mbase = mask + b * SS;

    unsigned long long acc0p[16], acc1p[16];
    #pragma unroll
    for (int c = 0; c < 16; c++) { acc0p[c] = 0ull; acc1p[c] = 0ull; }
    float m0 = -1e30f, l0 = 0.f;
    float m1 = -1e30f, l1 = 0.f;

    const int jmax = q0 + 127;
    for (int j0 = 0; j0 <= jmax; j0 += 64) {
        for (int t = tid; t < 512; t += 128) {
            int row = t >> 3, c = t & 7;
            Ks[row][c] = ((const float4*)(kbase + (j0 + row) * HD))[c];
            Vs[row][c] = ((const float4*)(vbase + (j0 + row) * HD))[c];
        }
        if (tid < 64) smask[tid] = mbase[j0 + tid];
        __syncthreads();

        #pragma unroll 1
        for (int jc = 0; jc < 64; jc += 8) {
            float s0[8], s1[8];
            float t0m = -1e30f, t1m = -1e30f;
            #pragma unroll
            for (int j = 0; j < 8; j++) {
                int jj = jc + j;
                const ulonglong2* kp = (const ulonglong2*)&Ks[jj][0];
                unsigned long long d0 = 0ull, d1 = 0ull;
                #pragma unroll
                for (int c = 0; c < 8; c++) {
                    ulonglong2 kv = kp[c];
                    FMA2(d0, qa2[2*c],   kv.x);
                    FMA2(d0, qa2[2*c+1], kv.y);
                    FMA2(d1, qb2[2*c],   kv.x);
                    FMA2(d1, qb2[2*c+1], kv.y);
                }
                float2 f0 = *(float2*)&d0;
                float2 f1 = *(float2*)&d1;
                float dot0 = f0.x + f0.y;
                float dot1 = f1.x + f1.y;
                bool ok = (j0 + jj <= r) && (smask[jj] != 0);
                s0[j] = ok ? dot0 : -1e9f;  t0m = fmaxf(t0m, s0[j]);
                s1[j] = ok ? dot1 : -1e9f;  t1m = fmaxf(t1m, s1[j]);
            }
            // conditional rescale (max update is rare: ~ln(S) per row)
            if (t0m > m0) {
                float corr = __expf(m0 - t0m);
                l0 *= corr;
                unsigned long long cd; DUP2(cd, corr);
                #pragma unroll
                for (int c = 0; c < 16; c++) MUL2(acc0p[c], cd);
                m0 = t0m;
            }
            if (t1m > m1) {
                float corr = __expf(m1 - t1m);
                l1 *= corr;
                unsigned long long cd; DUP2(cd, corr);
                #pragma unroll
                for (int c = 0; c < 16; c++) MUL2(acc1p[c], cd);
                m1 = t1m;
            }
            #pragma unroll
            for (int j = 0; j < 8; j++) {
                float p0 = __expf(s0[j] - m0);  l0 += p0;
                float p1 = __expf(s1[j] - m1);  l1 += p1;
                unsigned long long p0d, p1d;
                DUP2(p0d, p0);
                DUP2(p1d, p1);
                int jj = jc + j;
                const ulonglong2* vp = (const ulonglong2*)&Vs[jj][0];
                #pragma unroll
                for (int c = 0; c < 8; c++) {
                    ulonglong2 vv = vp[c];
                    FMA2(acc0p[2*c],   p0d, vv.x);
                    FMA2(acc0p[2*c+1], p0d, vv.y);
                    FMA2(acc1p[2*c],   p1d, vv.x);
                    FMA2(acc1p[2*c+1], p1d, vv.y);
                }
            }
        }
        __syncthreads();
    }

    float i0 = 1.0f / l0;
    float i1 = 1.0f / l1;
    float* op = g_ao + (b * SS + r) * DMODEL + h0 * HD;  // heads contiguous
    #pragma unroll
    for (int c = 0; c < 8; c++) {
        float2 xa = *(float2*)&acc0p[2*c];
        float2 ya = *(float2*)&acc0p[2*c+1];
        ((float4*)op)[c] = make_float4(xa.x * i0, xa.y * i0, ya.x * i0, ya.y * i0);
        float2 xb = *(float2*)&acc1p[2*c];
        float2 yb = *(float2*)&acc1p[2*c+1];
        ((float4*)(op + HD))[c] = make_float4(xb.x * i1, xb.y * i1, yb.x * i1, yb.y * i1);
    }
}

// ---------------- launch ----------------
extern "C" void kernel_launch(void* const* d_in, const int* in_sizes, int n_in,
                              void* d_out, int out_size) {
    const float* hs  = (const float*)d_in[0];
    const int*   msk = (const int*)  d_in[1];
    const float* Wq  = (const float*)d_in[2];
    const float* Wk  = (const float*)d_in[3];
    const float* Wv  = (const float*)d_in[4];
    const float* Wo  = (const float*)d_in[5];
    float* out = (float*)d_out;

    gemm_qkv<<<dim3(1536 / GBN, (BB * SS) / GBM), 256>>>(hs, Wq, Wk, Wv);

    int ropeThreads = (BB * HQ * SS + BB * HKV * SS) * 16;
    rope_kernel<<<(ropeThreads + 255) / 256, 256>>>();

    attention_kernel<<<dim3(SS / 128, HQ / 2, BB), 128>>>(msk);

    gemm_out<<<dim3(DMODEL / GBN, (BB * SS) / GBM), 256>>>(Wo, out);
}

// round 13
// speedup vs baseline: 1.5242x; 1.5242x over previous
#include <cuda_runtime.h>
#include <cuda_bf16.h>
#include <math.h>
#include <stdint.h>

#define BB     2
#define SS     2048
#define DMODEL 1024
#define HQ     32
#define HKV    8
#define HD     32

// ---------------- scratch (no allocs allowed) ----------------
__device__ float g_q [BB*HQ *SS*HD];   // [b][h][s][d]
__device__ float g_k [BB*HKV*SS*HD];
__device__ float g_v [BB*HKV*SS*HD];
__device__ float g_ao[BB*SS*DMODEL];   // attention out, [b][s][h*HD+d]

// bf16 split-precision operands (hi/lo)
__device__ __align__(16) __nv_bfloat16 g_hsh[BB*SS*DMODEL];
__device__ __align__(16) __nv_bfloat16 g_hsl[BB*SS*DMODEL];
__device__ __align__(16) __nv_bfloat16 g_wh [1536*DMODEL];   // Wq|Wk|Wv rows
__device__ __align__(16) __nv_bfloat16 g_wl [1536*DMODEL];
__device__ __align__(16) __nv_bfloat16 g_woh[DMODEL*DMODEL];
__device__ __align__(16) __nv_bfloat16 g_wol[DMODEL*DMODEL];
__device__ __align__(16) __nv_bfloat16 g_aoh[BB*SS*DMODEL];
__device__ __align__(16) __nv_bfloat16 g_aol[BB*SS*DMODEL];

__device__ __forceinline__ uint32_t smem_u32(const void* p) {
    uint32_t a;
    asm("{ .reg .u64 t; cvta.to.shared.u64 t, %1; cvt.u32.u64 %0, t; }"
        : "=r"(a) : "l"(p));
    return a;
}
__device__ __forceinline__ void ldsm4(uint32_t& r0, uint32_t& r1,
                                      uint32_t& r2, uint32_t& r3, uint32_t addr) {
    asm volatile("ldmatrix.sync.aligned.m8n8.x4.shared.b16 {%0,%1,%2,%3}, [%4];"
                 : "=r"(r0), "=r"(r1), "=r"(r2), "=r"(r3) : "r"(addr));
}
__device__ __forceinline__ void mma16816(float* c, const uint32_t* a, const uint32_t* b) {
    asm volatile(
        "mma.sync.aligned.m16n8k16.row.col.f32.bf16.bf16.f32 "
        "{%0,%1,%2,%3}, {%4,%5,%6,%7}, {%8,%9}, {%0,%1,%2,%3};"
        : "+f"(c[0]), "+f"(c[1]), "+f"(c[2]), "+f"(c[3])
        : "r"(a[0]), "r"(a[1]), "r"(a[2]), "r"(a[3]), "r"(b[0]), "r"(b[1]));
}

// ---------------- split fp32 -> (hi, lo) bf16 ----------------
// which: 0=hs, 1=Wq(row 0), 2=Wk(row 1024), 3=Wv(row 1280), 4=Wo, 5=g_ao
__global__ void split_bf16(const float* __restrict__ src, int which, int n4) {
    int i = blockIdx.x * 256 + threadIdx.x;
    if (i >= n4) return;
    __nv_bfloat16 *ho, *lo;
    const float* s = src;
    switch (which) {
        case 0:  ho = g_hsh;              lo = g_hsl;              break;
        case 1:  ho = g_wh;               lo = g_wl;               break;
        case 2:  ho = g_wh + 1024*1024;   lo = g_wl + 1024*1024;   break;
        case 3:  ho = g_wh + 1280*1024;   lo = g_wl + 1280*1024;   break;
        case 4:  ho = g_woh;              lo = g_wol;              break;
        default: ho = g_aoh;              lo = g_aol; s = g_ao;    break;
    }
    float4 x = ((const float4*)s)[i];
    __nv_bfloat162 h01, h23, l01, l23;
    h01.x = __float2bfloat16(x.x); h01.y = __float2bfloat16(x.y);
    h23.x = __float2bfloat16(x.z); h23.y = __float2bfloat16(x.w);
    l01.x = __float2bfloat16(x.x - __bfloat162float(h01.x));
    l01.y = __float2bfloat16(x.y - __bfloat162float(h01.y));
    l23.x = __float2bfloat16(x.z - __bfloat162float(h23.x));
    l23.y = __float2bfloat16(x.w - __bfloat162float(h23.y));
    ((__nv_bfloat162*)ho)[2*i]   = h01;
    ((__nv_bfloat162*)ho)[2*i+1] = h23;
    ((__nv_bfloat162*)lo)[2*i]   = l01;
    ((__nv_bfloat162*)lo)[2*i+1] = l23;
}

// ---------------- HMMA split-bf16 GEMM ----------------
// C[m,n] = sum_k A[m,k]*B[n,k]; fp32 via Ah*Bh + Ah*Bl + Al*Bh.
// mode 0: A=hs split, B=g_wh/g_wl (1536 rows), scatter into g_q/g_k/g_v
// mode 1: A=ao split, B=wo split, plain write to Cout
#define BM 128
#define BN 128
#define BK 32
#define APAD 8
#define AST (BK + APAD)            // 40 bf16 = 80B row stride (conflict-free ldsm)
#define KT  (DMODEL / BK)          // 32 tiles per pass

__global__ __launch_bounds__(256) void gemm_mma(int mode, float* __restrict__ Cout) {
    __shared__ __align__(16) __nv_bfloat16 smA[BM][AST];
    __shared__ __align__(16) __nv_bfloat16 smB[BN][AST];

    const int tid    = threadIdx.x;
    const int lane   = tid & 31;
    const int wid    = tid >> 5;
    const int warp_m = wid & 1;        // 2 x 64 rows
    const int warp_n = wid >> 1;       // 4 x 32 cols
    const int m0     = blockIdx.y * BM;
    const int n0     = blockIdx.x * BN;

    const __nv_bfloat16* Ah = (mode == 0) ? g_hsh : g_aoh;
    const __nv_bfloat16* Al = (mode == 0) ? g_hsl : g_aol;
    const __nv_bfloat16* Bh = (mode == 0) ? g_wh  : g_woh;
    const __nv_bfloat16* Bl = (mode == 0) ? g_wl  : g_wol;
    const __nv_bfloat16* Ap[3] = {Ah, Ah, Al};
    const __nv_bfloat16* Bp[3] = {Bh, Bl, Bh};

    float acc[4][4][4];
    #pragma unroll
    for (int mt = 0; mt < 4; mt++)
        #pragma unroll
        for (int nt = 0; nt < 4; nt++)
            #pragma unroll
            for (int c = 0; c < 4; c++) acc[mt][nt][c] = 0.f;

    const int lrow = tid >> 2;         // 0..63
    const int lseg = tid & 3;          // 0..3 (8 bf16 each)

    int4 ra0, ra1, rb0, rb1;
    {   // prefetch tile 0 (pass 0, kc 0)
        const __nv_bfloat16* As = Ap[0];
        const __nv_bfloat16* Bs = Bp[0];
        ra0 = *(const int4*)(As + (m0 + lrow)      * DMODEL + lseg * 8);
        ra1 = *(const int4*)(As + (m0 + lrow + 64) * DMODEL + lseg * 8);
        rb0 = *(const int4*)(Bs + (n0 + lrow)      * DMODEL + lseg * 8);
        rb1 = *(const int4*)(Bs + (n0 + lrow + 64) * DMODEL + lseg * 8);
    }

    const int NG = 3 * KT;             // 96
    for (int g = 0; g < NG; g++) {
        *(int4*)&smA[lrow][lseg * 8]      = ra0;
        *(int4*)&smA[lrow + 64][lseg * 8] = ra1;
        *(int4*)&smB[lrow][lseg * 8]      = rb0;
        *(int4*)&smB[lrow + 64][lseg * 8] = rb1;
        __syncthreads();

        if (g + 1 < NG) {
            int gn = g + 1;
            const __nv_bfloat16* As = Ap[gn >> 5];
            const __nv_bfloat16* Bs = Bp[gn >> 5];
            int ko = (gn & 31) * BK + lseg * 8;
            ra0 = *(const int4*)(As + (m0 + lrow)      * DMODEL + ko);
            ra1 = *(const int4*)(As + (m0 + lrow + 64) * DMODEL + ko);
            rb0 = *(const int4*)(Bs + (n0 + lrow)      * DMODEL + ko);
            rb1 = *(const int4*)(Bs + (n0 + lrow + 64) * DMODEL + ko);
        }

        #pragma unroll
        for (int ks = 0; ks < 2; ks++) {
            uint32_t af[4][4], bf[4][2];
            #pragma unroll
            for (int mt = 0; mt < 4; mt++) {
                int row = warp_m * 64 + mt * 16 + (lane & 15);
                int col = ks * 16 + (lane >> 4) * 8;
                ldsm4(af[mt][0], af[mt][1], af[mt][2], af[mt][3],
                      smem_u32(&smA[row][col]));
            }
            #pragma unroll
            for (int nt2 = 0; nt2 < 2; nt2++) {
                int nrow = warp_n * 32 + nt2 * 16 + (lane >> 4) * 8 + (lane & 7);
                int col  = ks * 16 + ((lane >> 3) & 1) * 8;
                ldsm4(bf[2*nt2][0], bf[2*nt2][1], bf[2*nt2+1][0], bf[2*nt2+1][1],
                      smem_u32(&smB[nrow][col]));
            }
            #pragma unroll
            for (int mt = 0; mt < 4; mt++)
                #pragma unroll
                for (int nt = 0; nt < 4; nt++)
                    mma16816(acc[mt][nt], af[mt], bf[nt]);
        }
        __syncthreads();
    }

    // epilogue: c0,c1 -> (row gid, cols 2tig,2tig+1); c2,c3 -> row gid+8
    const int gid = lane >> 2;
    const int tig = lane & 3;
    #pragma unroll
    for (int mt = 0; mt < 4; mt++) {
        int mrow = m0 + warp_m * 64 + mt * 16 + gid;
        #pragma unroll
        for (int nt = 0; nt < 4; nt++) {
            int nl = n0 + warp_n * 32 + nt * 8 + 2 * tig;
            #pragma unroll
            for (int half = 0; half < 2; half++) {
                int m = mrow + half * 8;
                float2 v = make_float2(acc[mt][nt][2*half], acc[mt][nt][2*half+1]);
                float* o;
                if (mode == 1) {
                    o = Cout + m * DMODEL + nl;
                } else {
                    int b = m >> 11, s = m & (SS - 1);
                    if (nl < 1024)
                        o = g_q + ((b * HQ + (nl >> 5)) * SS + s) * HD + (nl & 31);
                    else if (nl < 1280) {
                        int t = nl - 1024;
                        o = g_k + ((b * HKV + (t >> 5)) * SS + s) * HD + (t & 31);
                    } else {
                        int t = nl - 1280;
                        o = g_v + ((b * HKV + (t >> 5)) * SS + s) * HD + (t & 31);
                    }
                }
                *(float2*)o = v;
            }
        }
    }
}

// ---------------- RoPE over g_q and g_k ----------------
__global__ void rope_kernel() {
    const int NQROWS = BB * HQ * SS;
    const int TOT    = (NQROWS + BB * HKV * SS) * 16;
    int gid = blockIdx.x * blockDim.x + threadIdx.x;
    if (gid >= TOT) return;
    int row = gid >> 4;
    int i   = gid & 15;
    float* base = (row < NQROWS) ? (g_q + row * HD)
                                 : (g_k + (row - NQROWS) * HD);
    int s = row & (SS - 1);
    float inv_freq = expf(-(float)i * (9.210340371976184f / 16.0f));
    float ang = (float)s * inv_freq;
    float c, sn;
    sincosf(ang, &sn, &c);
    float x1 = base[i];
    float x2 = base[i + 16];
    base[i]      = x1 * c - x2 * sn;
    base[i + 16] = x2 * c + x1 * sn;
}

// ---------------- causal GQA flash attention (known-good) ----------------
__global__ __launch_bounds__(128, 1) void attention_kernel(const int* __restrict__ mask) {
    const int b   = blockIdx.z;
    const int h0  = blockIdx.y * 2;          // heads h0, h0+1 share kv head
    const int q0  = blockIdx.x * 128;
    const int tid = threadIdx.x;
    const int r   = q0 + tid;
    const int kvh = h0 >> 2;                 // GROUP = 4
    const float scale = 0.17677669529663687f; // 1/sqrt(32)

    __shared__ float4 Ks[64][8];
    __shared__ float4 Vs[64][8];
    __shared__ int smask[64];

    const float* qp0 = g_q + ((b * HQ + h0    ) * SS + r) * HD;
    const float* qp1 = g_q + ((b * HQ + h0 + 1) * SS + r) * HD;
    float4 qa[8], qb[8];
    #pragma unroll
    for (int c = 0; c < 8; c++) {
        qa[c] = ((const float4*)qp0)[c];
        qa[c].x *= scale; qa[c].y *= scale; qa[c].z *= scale; qa[c].w *= scale;
        qb[c] = ((const float4*)qp1)[c];
        qb[c].x *= scale; qb[c].y *= scale; qb[c].z *= scale; qb[c].w *= scale;
    }

    const float* kbase = g_k + (b * HKV + kvh) * SS * HD;
    const float* vbase = g_v + (b * HKV + kvh) * SS * HD;
    const int*   mbase = mask + b * SS;

    float4 acc0[8], acc1[8];
    #pragma unroll
    for (int c = 0; c < 8; c++) {
        acc0[c] = make_float4(0.f, 0.f, 0.f, 0.f);
        acc1[c] = make_float4(0.f, 0.f, 0.f, 0.f);
    }
    float m0 = -1e30f, l0 = 0.f;
    float m1 = -1e30f, l1 = 0.f;

    const int jmax = q0 + 127;
    for (int j0 = 0; j0 <= jmax; j0 += 64) {
        for (int t = tid; t < 512; t += 128) {
            int row = t >> 3, c = t & 7;
            Ks[row][c] = ((const float4*)(kbase + (j0 + row) * HD))[c];
            Vs[row][c] = ((const float4*)(vbase + (j0 + row) * HD))[c];
        }
        if (tid < 64) smask[tid] = mbase[j0 + tid];
        __syncthreads();

        #pragma unroll 1
        for (int jc = 0; jc < 64; jc += 8) {
            float s0[8], s1[8];
            float t0 = -1e30f, t1 = -1e30f;
            #pragma unroll
            for (int j = 0; j < 8; j++) {
                int jj = jc + j;
                float4 d0 = make_float4(0.f, 0.f, 0.f, 0.f);
                float4 d1 = make_float4(0.f, 0.f, 0.f, 0.f);
                #pragma unroll
                for (int c = 0; c < 8; c++) {
                    float4 kv = Ks[jj][c];
                    d0.x += qa[c].x * kv.x; d0.y += qa[c].y * kv.y;
                    d0.z += qa[c].z * kv.z; d0.w += qa[c].w * kv.w;
                    d1.x += qb[c].x * kv.x; d1.y += qb[c].y * kv.y;
                    d1.z += qb[c].z * kv.z; d1.w += qb[c].w * kv.w;
                }
                float dot0 = (d0.x + d0.y) + (d0.z + d0.w);
                float dot1 = (d1.x + d1.y) + (d1.z + d1.w);
                bool ok = (j0 + jj <= r) && (smask[jj] != 0);
                s0[j] = ok ? dot0 : -1e9f;  t0 = fmaxf(t0, s0[j]);
                s1[j] = ok ? dot1 : -1e9f;  t1 = fmaxf(t1, s1[j]);
            }
            if (t0 > m0) {
                float corr = __expf(m0 - t0);
                l0 *= corr;
                #pragma unroll
                for (int c = 0; c < 8; c++) {
                    acc0[c].x *= corr; acc0[c].y *= corr;
                    acc0[c].z *= corr; acc0[c].w *= corr;
                }
                m0 = t0;
            }
            if (t1 > m1) {
                float corr = __expf(m1 - t1);
                l1 *= corr;
                #pragma unroll
                for (int c = 0; c < 8; c++) {
                    acc1[c].x *= corr; acc1[c].y *= corr;
                    acc1[c].z *= corr; acc1[c].w *= corr;
                }
                m1 = t1;
            }
            #pragma unroll
            for (int j = 0; j < 8; j++) {
                float p0 = __expf(s0[j] - m0);  l0 += p0;
                float p1 = __expf(s1[j] - m1);  l1 += p1;
                int jj = jc + j;
                #pragma unroll
                for (int c = 0; c < 8; c++) {
                    float4 vv = Vs[jj][c];
                    acc0[c].x += p0 * vv.x; acc0[c].y += p0 * vv.y;
                    acc0[c].z += p0 * vv.z; acc0[c].w += p0 * vv.w;
                    acc1[c].x += p1 * vv.x; acc1[c].y += p1 * vv.y;
                    acc1[c].z += p1 * vv.z; acc1[c].w += p1 * vv.w;
                }
            }
        }
        __syncthreads();
    }

    float i0 = 1.0f / l0;
    float i1 = 1.0f / l1;
    float* op = g_ao + (b * SS + r) * DMODEL + h0 * HD;
    #pragma unroll
    for (int c = 0; c < 8; c++) {
        float4 o = acc0[c];
        o.x *= i0; o.y *= i0; o.z *= i0; o.w *= i0;
        ((float4*)op)[c] = o;
        float4 o1 = acc1[c];
        o1.x *= i1; o1.y *= i1; o1.z *= i1; o1.w *= i1;
        ((float4*)(op + HD))[c] = o1;
    }
}

// ---------------- launch ----------------
extern "C" void kernel_launch(void* const* d_in, const int* in_sizes, int n_in,
                              void* d_out, int out_size) {
    const float* hs  = (const float*)d_in[0];
    const int*   msk = (const int*)  d_in[1];
    const float* Wq  = (const float*)d_in[2];
    const float* Wk  = (const float*)d_in[3];
    const float* Wv  = (const float*)d_in[4];
    const float* Wo  = (const float*)d_in[5];
    float* out = (float*)d_out;

    // split fp32 -> (hi, lo) bf16
    split_bf16<<<(1048576 + 255) / 256, 256>>>(hs, 0, 1048576);
    split_bf16<<<(262144  + 255) / 256, 256>>>(Wq, 1, 262144);
    split_bf16<<<(65536   + 255) / 256, 256>>>(Wk, 2, 65536);
    split_bf16<<<(65536   + 255) / 256, 256>>>(Wv, 3, 65536);
    split_bf16<<<(262144  + 255) / 256, 256>>>(Wo, 4, 262144);

    // QKV projection on HMMA tensor cores (N = 1536)
    gemm_mma<<<dim3(1536 / BN, (BB * SS) / BM), 256>>>(0, nullptr);

    // RoPE on q and k
    int ropeThreads = (BB * HQ * SS + BB * HKV * SS) * 16;
    rope_kernel<<<(ropeThreads + 255) / 256, 256>>>();

    // causal GQA attention
    attention_kernel<<<dim3(SS / 128, HQ / 2, BB), 128>>>(msk);

    // split attention output, then output projection on HMMA
    split_bf16<<<(1048576 + 255) / 256, 256>>>(nullptr, 5, 1048576);
    gemm_mma<<<dim3(DMODEL / BN, (BB * SS) / BM), 256>>>(1, out);
}

// round 15
// speedup vs baseline: 2.7226x; 1.7863x over previous
#include <cuda_runtime.h>
#include <cuda_bf16.h>
#include <cuda_fp16.h>
#include <math.h>
#include <stdint.h>

#define BB     2
#define SS     2048
#define DMODEL 1024
#define HQ     32
#define HKV    8
#define HD     32

// ---------------- scratch (no allocs allowed) ----------------
__device__ float g_q [BB*HQ *SS*HD];   // [b][h][s][d] fp32 (pre-rope)
__device__ float g_k [BB*HKV*SS*HD];
__device__ float g_v [BB*HKV*SS*HD];
__device__ float g_ao[BB*SS*DMODEL];   // attention out, [b][s][h*HD+d]

// fp16 attention operands
__device__ __align__(16) __half g_q16 [BB*HQ *SS*HD];  // roped, pre-scaled
__device__ __align__(16) __half g_k16 [BB*HKV*SS*HD];  // roped
__device__ __align__(16) __half g_vh16[BB*HKV*SS*HD];
__device__ __align__(16) __half g_vl16[BB*HKV*SS*HD];

// bf16 split-precision operands (hi/lo) for projections
__device__ __align__(16) __nv_bfloat16 g_hsh[BB*SS*DMODEL];
__device__ __align__(16) __nv_bfloat16 g_hsl[BB*SS*DMODEL];
__device__ __align__(16) __nv_bfloat16 g_wh [1536*DMODEL];
__device__ __align__(16) __nv_bfloat16 g_wl [1536*DMODEL];
__device__ __align__(16) __nv_bfloat16 g_woh[DMODEL*DMODEL];
__device__ __align__(16) __nv_bfloat16 g_wol[DMODEL*DMODEL];
__device__ __align__(16) __nv_bfloat16 g_aoh[BB*SS*DMODEL];
__device__ __align__(16) __nv_bfloat16 g_aol[BB*SS*DMODEL];

__device__ __forceinline__ uint32_t smem_u32(const void* p) {
    uint32_t a;
    asm("{ .reg .u64 t; cvta.to.shared.u64 t, %1; cvt.u32.u64 %0, t; }"
        : "=r"(a) : "l"(p));
    return a;
}
__device__ __forceinline__ void ldsm4(uint32_t& r0, uint32_t& r1,
                                      uint32_t& r2, uint32_t& r3, uint32_t addr) {
    asm volatile("ldmatrix.sync.aligned.m8n8.x4.shared.b16 {%0,%1,%2,%3}, [%4];"
                 : "=r"(r0), "=r"(r1), "=r"(r2), "=r"(r3) : "r"(addr));
}
__device__ __forceinline__ void ldsm4t(uint32_t& r0, uint32_t& r1,
                                       uint32_t& r2, uint32_t& r3, uint32_t addr) {
    asm volatile("ldmatrix.sync.aligned.m8n8.x4.trans.shared.b16 {%0,%1,%2,%3}, [%4];"
                 : "=r"(r0), "=r"(r1), "=r"(r2), "=r"(r3) : "r"(addr));
}
__device__ __forceinline__ void mma16816(float* c, const uint32_t* a, const uint32_t* b) {
    asm volatile(
        "mma.sync.aligned.m16n8k16.row.col.f32.bf16.bf16.f32 "
        "{%0,%1,%2,%3}, {%4,%5,%6,%7}, {%8,%9}, {%0,%1,%2,%3};"
        : "+f"(c[0]), "+f"(c[1]), "+f"(c[2]), "+f"(c[3])
        : "r"(a[0]), "r"(a[1]), "r"(a[2]), "r"(a[3]), "r"(b[0]), "r"(b[1]));
}
__device__ __forceinline__ void mma16816h(float* c, const uint32_t* a,
                                          uint32_t b0, uint32_t b1) {
    asm volatile(
        "mma.sync.aligned.m16n8k16.row.col.f32.f16.f16.f32 "
        "{%0,%1,%2,%3}, {%4,%5,%6,%7}, {%8,%9}, {%0,%1,%2,%3};"
        : "+f"(c[0]), "+f"(c[1]), "+f"(c[2]), "+f"(c[3])
        : "r"(a[0]), "r"(a[1]), "r"(a[2]), "r"(a[3]), "r"(b0), "r"(b1));
}

// ---------------- split fp32 -> (hi, lo) bf16 ----------------
__global__ void split_bf16(const float* __restrict__ src, int which, int n4) {
    int i = blockIdx.x * 256 + threadIdx.x;
    if (i >= n4) return;
    __nv_bfloat16 *ho, *lo;
    const float* s = src;
    switch (which) {
        case 0:  ho = g_hsh;              lo = g_hsl;              break;
        case 1:  ho = g_wh;               lo = g_wl;               break;
        case 2:  ho = g_wh + 1024*1024;   lo = g_wl + 1024*1024;   break;
        case 3:  ho = g_wh + 1280*1024;   lo = g_wl + 1280*1024;   break;
        case 4:  ho = g_woh;              lo = g_wol;              break;
        default: ho = g_aoh;              lo = g_aol; s = g_ao;    break;
    }
    float4 x = ((const float4*)s)[i];
    __nv_bfloat162 h01, h23, l01, l23;
    h01.x = __float2bfloat16(x.x); h01.y = __float2bfloat16(x.y);
    h23.x = __float2bfloat16(x.z); h23.y = __float2bfloat16(x.w);
    l01.x = __float2bfloat16(x.x - __bfloat162float(h01.x));
    l01.y = __float2bfloat16(x.y - __bfloat162float(h01.y));
    l23.x = __float2bfloat16(x.z - __bfloat162float(h23.x));
    l23.y = __float2bfloat16(x.w - __bfloat162float(h23.y));
    ((__nv_bfloat162*)ho)[2*i]   = h01;
    ((__nv_bfloat162*)ho)[2*i+1] = h23;
    ((__nv_bfloat162*)lo)[2*i]   = l01;
    ((__nv_bfloat162*)lo)[2*i+1] = l23;
}

// ---------------- HMMA split-bf16 GEMM (unchanged from passing R13) ----------------
#define BM 128
#define BN 128
#define BK 32
#define APAD 8
#define AST (BK + APAD)
#define KT  (DMODEL / BK)

__global__ __launch_bounds__(256) void gemm_mma(int mode, float* __restrict__ Cout) {
    __shared__ __align__(16) __nv_bfloat16 smA[BM][AST];
    __shared__ __align__(16) __nv_bfloat16 smB[BN][AST];

    const int tid    = threadIdx.x;
    const int lane   = tid & 31;
    const int wid    = tid >> 5;
    const int warp_m = wid & 1;
    const int warp_n = wid >> 1;
    const int m0     = blockIdx.y * BM;
    const int n0     = blockIdx.x * BN;

    const __nv_bfloat16* Ah = (mode == 0) ? g_hsh : g_aoh;
    const __nv_bfloat16* Al = (mode == 0) ? g_hsl : g_aol;
    const __nv_bfloat16* Bh = (mode == 0) ? g_wh  : g_woh;
    const __nv_bfloat16* Bl = (mode == 0) ? g_wl  : g_wol;
    const __nv_bfloat16* Ap[3] = {Ah, Ah, Al};
    const __nv_bfloat16* Bp[3] = {Bh, Bl, Bh};

    float acc[4][4][4];
    #pragma unroll
    for (int mt = 0; mt < 4; mt++)
        #pragma unroll
        for (int nt = 0; nt < 4; nt++)
            #pragma unroll
            for (int c = 0; c < 4; c++) acc[mt][nt][c] = 0.f;

    const int lrow = tid >> 2;
    const int lseg = tid & 3;

    int4 ra0, ra1, rb0, rb1;
    {
        const __nv_bfloat16* As = Ap[0];
        const __nv_bfloat16* Bs = Bp[0];
        ra0 = *(const int4*)(As + (m0 + lrow)      * DMODEL + lseg * 8);
        ra1 = *(const int4*)(As + (m0 + lrow + 64) * DMODEL + lseg * 8);
        rb0 = *(const int4*)(Bs + (n0 + lrow)      * DMODEL + lseg * 8);
        rb1 = *(const int4*)(Bs + (n0 + lrow + 64) * DMODEL + lseg * 8);
    }

    const int NG = 3 * KT;
    for (int g = 0; g < NG; g++) {
        *(int4*)&smA[lrow][lseg * 8]      = ra0;
        *(int4*)&smA[lrow + 64][lseg * 8] = ra1;
        *(int4*)&smB[lrow][lseg * 8]      = rb0;
        *(int4*)&smB[lrow + 64][lseg * 8] = rb1;
        __syncthreads();

        if (g + 1 < NG) {
            int gn = g + 1;
            const __nv_bfloat16* As = Ap[gn >> 5];
            const __nv_bfloat16* Bs = Bp[gn >> 5];
            int ko = (gn & 31) * BK + lseg * 8;
            ra0 = *(const int4*)(As + (m0 + lrow)      * DMODEL + ko);
            ra1 = *(const int4*)(As + (m0 + lrow + 64) * DMODEL + ko);
            rb0 = *(const int4*)(Bs + (n0 + lrow)      * DMODEL + ko);
            rb1 = *(const int4*)(Bs + (n0 + lrow + 64) * DMODEL + ko);
        }

        #pragma unroll
        for (int ks = 0; ks < 2; ks++) {
            uint32_t af[4][4], bf[4][2];
            #pragma unroll
            for (int mt = 0; mt < 4; mt++) {
                int row = warp_m * 64 + mt * 16 + (lane & 15);
                int col = ks * 16 + (lane >> 4) * 8;
                ldsm4(af[mt][0], af[mt][1], af[mt][2], af[mt][3],
                      smem_u32(&smA[row][col]));
            }
            #pragma unroll
            for (int nt2 = 0; nt2 < 2; nt2++) {
                int nrow = warp_n * 32 + nt2 * 16 + (lane >> 4) * 8 + (lane & 7);
                int col  = ks * 16 + ((lane >> 3) & 1) * 8;
                ldsm4(bf[2*nt2][0], bf[2*nt2][1], bf[2*nt2+1][0], bf[2*nt2+1][1],
                      smem_u32(&smB[nrow][col]));
            }
            #pragma unroll
            for (int mt = 0; mt < 4; mt++)
                #pragma unroll
                for (int nt = 0; nt < 4; nt++)
                    mma16816(acc[mt][nt], af[mt], bf[nt]);
        }
        __syncthreads();
    }

    const int gid = lane >> 2;
    const int tig = lane & 3;
    #pragma unroll
    for (int mt = 0; mt < 4; mt++) {
        int mrow = m0 + warp_m * 64 + mt * 16 + gid;
        #pragma unroll
        for (int nt = 0; nt < 4; nt++) {
            int nl = n0 + warp_n * 32 + nt * 8 + 2 * tig;
            #pragma unroll
            for (int half = 0; half < 2; half++) {
                int m = mrow + half * 8;
                float2 v = make_float2(acc[mt][nt][2*half], acc[mt][nt][2*half+1]);
                float* o;
                if (mode == 1) {
                    o = Cout + m * DMODEL + nl;
                } else {
                    int b = m >> 11, s = m & (SS - 1);
                    if (nl < 1024)
                        o = g_q + ((b * HQ + (nl >> 5)) * SS + s) * HD + (nl & 31);
                    else if (nl < 1280) {
                        int t = nl - 1024;
                        o = g_k + ((b * HKV + (t >> 5)) * SS + s) * HD + (t & 31);
                    } else {
                        int t = nl - 1280;
                        o = g_v + ((b * HKV + (t >> 5)) * SS + s) * HD + (t & 31);
                    }
                }
                *(float2*)o = v;
            }
        }
    }
}

// ---------------- RoPE fp32 -> fp16 (Q pre-scaled) ----------------
__global__ void rope_f16() {
    const int NQROWS = BB * HQ * SS;
    const int TOT    = (NQROWS + BB * HKV * SS) * 16;
    int gid = blockIdx.x * blockDim.x + threadIdx.x;
    if (gid >= TOT) return;
    int row = gid >> 4;
    int i   = gid & 15;
    const float* src;
    __half* dst;
    float postscale;
    if (row < NQROWS) {
        src = g_q + row * HD;  dst = g_q16 + row * HD;
        postscale = 0.17677669529663687f;   // 1/sqrt(32)
    } else {
        int kr = row - NQROWS;
        src = g_k + kr * HD;   dst = g_k16 + kr * HD;
        postscale = 1.0f;
    }
    int s = row & (SS - 1);
    float inv_freq = expf(-(float)i * (9.210340371976184f / 16.0f));
    float ang = (float)s * inv_freq;
    float c, sn;
    sincosf(ang, &sn, &c);
    float x1 = src[i];
    float x2 = src[i + 16];
    dst[i]      = __float2half((x1 * c - x2 * sn) * postscale);
    dst[i + 16] = __float2half((x2 * c + x1 * sn) * postscale);
}

// ---------------- V fp32 -> fp16 hi/lo ----------------
__global__ void vconv(int n4) {
    int i = blockIdx.x * 256 + threadIdx.x;
    if (i >= n4) return;
    float4 x = ((const float4*)g_v)[i];
    __half2 h01 = __floats2half2_rn(x.x, x.y);
    __half2 h23 = __floats2half2_rn(x.z, x.w);
    float2 f01 = __half22float2(h01);
    float2 f23 = __half22float2(h23);
    __half2 l01 = __floats2half2_rn(x.x - f01.x, x.y - f01.y);
    __half2 l23 = __floats2half2_rn(x.z - f23.x, x.w - f23.y);
    ((__half2*)g_vh16)[2*i]   = h01;
    ((__half2*)g_vh16)[2*i+1] = h23;
    ((__half2*)g_vl16)[2*i]   = l01;
    ((__half2*)g_vl16)[2*i+1] = l23;
}

// ---------------- HMMA causal GQA flash attention ----------------
// block: (b, kvh, 32-row q chunk) x 4 heads. 8 warps: warp w -> head kvh*4+(w>>1),
// rows q0+(w&1)*16 .. +15. K tiles of 64 keys staged in SMEM (stride 40 halves).
#define VST 40

__global__ __launch_bounds__(256) void attn_mma(const int* __restrict__ mask) {
    __shared__ __align__(16) __half sK [64][VST];
    __shared__ __align__(16) __half sVh[64][VST];
    __shared__ __align__(16) __half sVl[64][VST];
    __shared__ int smask[64];

    const int tid  = threadIdx.x;
    const int lane = tid & 31;
    const int w    = tid >> 5;
    const int b    = blockIdx.z;
    const int kvh  = blockIdx.y;
    const int q0   = blockIdx.x * 32;
    const int h    = kvh * 4 + (w >> 1);
    const int g    = lane >> 2;
    const int tig  = lane & 3;
    const int R0   = q0 + (w & 1) * 16 + g;
    const int R1   = R0 + 8;

    // Q A-fragments, loaded once (fp16, pre-scaled, roped)
    const __half* Qb = g_q16 + (size_t)(b * HQ + h) * SS * HD;
    uint32_t aQ[2][4];
    #pragma unroll
    for (int ks = 0; ks < 2; ks++) {
        aQ[ks][0] = *(const uint32_t*)(Qb + R0 * HD + ks * 16 + 2 * tig);
        aQ[ks][1] = *(const uint32_t*)(Qb + R1 * HD + ks * 16 + 2 * tig);
        aQ[ks][2] = *(const uint32_t*)(Qb + R0 * HD + ks * 16 + 2 * tig + 8);
        aQ[ks][3] = *(const uint32_t*)(Qb + R1 * HD + ks * 16 + 2 * tig + 8);
    }

    const __half* Kg  = g_k16  + (size_t)(b * HKV + kvh) * SS * HD;
    const __half* Vhg = g_vh16 + (size_t)(b * HKV + kvh) * SS * HD;
    const __half* Vlg = g_vl16 + (size_t)(b * HKV + kvh) * SS * HD;
    const int*    mb  = mask + b * SS;

    float O[4][4];
    #pragma unroll
    for (int nt = 0; nt < 4; nt++)
        #pragma unroll
        for (int c = 0; c < 4; c++) O[nt][c] = 0.f;
    float m0 = -1e30f, m1 = -1e30f, l0 = 0.f, l1 = 0.f;

    const int lr = tid >> 2;            // 0..63 (tile row)
    const int lg = (tid & 3) * 8;       // 8-half segment

    for (int j0 = 0; j0 < q0 + 32; j0 += 64) {
        *(int4*)&sK [lr][lg] = *(const int4*)(Kg  + (j0 + lr) * HD + lg);
        *(int4*)&sVh[lr][lg] = *(const int4*)(Vhg + (j0 + lr) * HD + lg);
        *(int4*)&sVl[lr][lg] = *(const int4*)(Vlg + (j0 + lr) * HD + lg);
        if (tid < 64) smask[tid] = mb[j0 + tid];
        __syncthreads();

        // ---- S = Q K^T ----
        float sf[8][4];
        #pragma unroll
        for (int nt = 0; nt < 8; nt++)
            #pragma unroll
            for (int c = 0; c < 4; c++) sf[nt][c] = 0.f;

        #pragma unroll
        for (int nt2 = 0; nt2 < 4; nt2++) {
            #pragma unroll
            for (int ks = 0; ks < 2; ks++) {
                uint32_t b0, b1, b2, b3;
                int nrow = nt2 * 16 + (lane >> 4) * 8 + (lane & 7);
                int col  = ks * 16 + ((lane >> 3) & 1) * 8;
                ldsm4(b0, b1, b2, b3, smem_u32(&sK[nrow][col]));
                mma16816h(sf[2*nt2],   aQ[ks], b0, b1);
                mma16816h(sf[2*nt2+1], aQ[ks], b2, b3);
            }
        }

        // ---- mask + row max ----
        float tm0 = -1e30f, tm1 = -1e30f;
        #pragma unroll
        for (int nt = 0; nt < 8; nt++) {
            int cb = nt * 8 + 2 * tig;
            #pragma unroll
            for (int cc = 0; cc < 2; cc++) {
                int cg = j0 + cb + cc;
                bool mk = smask[cb + cc] != 0;
                sf[nt][cc]     = (cg <= R0 && mk) ? sf[nt][cc]     : -1e9f;
                sf[nt][2 + cc] = (cg <= R1 && mk) ? sf[nt][2 + cc] : -1e9f;
                tm0 = fmaxf(tm0, sf[nt][cc]);
                tm1 = fmaxf(tm1, sf[nt][2 + cc]);
            }
        }
        tm0 = fmaxf(tm0, __shfl_xor_sync(0xFFFFFFFFu, tm0, 1));
        tm0 = fmaxf(tm0, __shfl_xor_sync(0xFFFFFFFFu, tm0, 2));
        tm1 = fmaxf(tm1, __shfl_xor_sync(0xFFFFFFFFu, tm1, 1));
        tm1 = fmaxf(tm1, __shfl_xor_sync(0xFFFFFFFFu, tm1, 2));

        // ---- online rescale ----
        if (tm0 > m0) {
            float cr = __expf(m0 - tm0);
            l0 *= cr;
            #pragma unroll
            for (int nt = 0; nt < 4; nt++) { O[nt][0] *= cr; O[nt][1] *= cr; }
            m0 = tm0;
        }
        if (tm1 > m1) {
            float cr = __expf(m1 - tm1);
            l1 *= cr;
            #pragma unroll
            for (int nt = 0; nt < 4; nt++) { O[nt][2] *= cr; O[nt][3] *= cr; }
            m1 = tm1;
        }

        // ---- P = exp(S - m), pack to fp16 hi/lo A-fragments ----
        float ls0 = 0.f, ls1 = 0.f;
        uint32_t aPh[4][4], aPl[4][4];
        #pragma unroll
        for (int nt = 0; nt < 8; nt++) {
            float p0 = __expf(sf[nt][0] - m0);
            float p1 = __expf(sf[nt][1] - m0);
            float p2 = __expf(sf[nt][2] - m1);
            float p3 = __expf(sf[nt][3] - m1);
            ls0 += p0 + p1;
            ls1 += p2 + p3;
            __half2 h01 = __floats2half2_rn(p0, p1);
            __half2 h23 = __floats2half2_rn(p2, p3);
            float2 f01 = __half22float2(h01);
            float2 f23 = __half22float2(h23);
            __half2 e01 = __floats2half2_rn(p0 - f01.x, p1 - f01.y);
            __half2 e23 = __floats2half2_rn(p2 - f23.x, p3 - f23.y);
            int kf = nt >> 1, pt = (nt & 1) * 2;
            aPh[kf][pt]     = *(uint32_t*)&h01;
            aPh[kf][pt + 1] = *(uint32_t*)&h23;
            aPl[kf][pt]     = *(uint32_t*)&e01;
            aPl[kf][pt + 1] = *(uint32_t*)&e23;
        }
        ls0 += __shfl_xor_sync(0xFFFFFFFFu, ls0, 1);
        ls0 += __shfl_xor_sync(0xFFFFFFFFu, ls0, 2);
        ls1 += __shfl_xor_sync(0xFFFFFFFFu, ls1, 1);
        ls1 += __shfl_xor_sync(0xFFFFFFFFu, ls1, 2);
        l0 += ls0;
        l1 += ls1;

        // ---- O += P V  (PhVh + PhVl + PlVh) ----
        const int vr = (lane & 7) + ((lane >> 3) & 1) * 8;
        const int vc = ((lane >> 4) & 1) * 8;
        #pragma unroll
        for (int kf = 0; kf < 4; kf++) {
            int kr = kf * 16 + vr;
            uint32_t v0, v1, v2, v3;
            ldsm4t(v0, v1, v2, v3, smem_u32(&sVh[kr][vc]));
            mma16816h(O[0], aPh[kf], v0, v1);
            mma16816h(O[1], aPh[kf], v2, v3);
            mma16816h(O[0], aPl[kf], v0, v1);
            mma16816h(O[1], aPl[kf], v2, v3);
            ldsm4t(v0, v1, v2, v3, smem_u32(&sVh[kr][16 + vc]));
            mma16816h(O[2], aPh[kf], v0, v1);
            mma16816h(O[3], aPh[kf], v2, v3);
            mma16816h(O[2], aPl[kf], v0, v1);
            mma16816h(O[3], aPl[kf], v2, v3);
            ldsm4t(v0, v1, v2, v3, smem_u32(&sVl[kr][vc]));
            mma16816h(O[0], aPh[kf], v0, v1);
            mma16816h(O[1], aPh[kf], v2, v3);
            ldsm4t(v0, v1, v2, v3, smem_u32(&sVl[kr][16 + vc]));
            mma16816h(O[2], aPh[kf], v0, v1);
            mma16816h(O[3], aPh[kf], v2, v3);
        }
        __syncthreads();
    }

    // ---- finalize ----
    float i0 = 1.0f / l0;
    float i1 = 1.0f / l1;
    float* o0 = g_ao + (size_t)(b * SS + R0) * DMODEL + h * HD + 2 * tig;
    float* o1 = g_ao + (size_t)(b * SS + R1) * DMODEL + h * HD + 2 * tig;
    #pragma unroll
    for (int nt = 0; nt < 4; nt++) {
        *(float2*)(o0 + nt * 8) = make_float2(O[nt][0] * i0, O[nt][1] * i0);
        *(float2*)(o1 + nt * 8) = make_float2(O[nt][2] * i1, O[nt][3] * i1);
    }
}

// ---------------- launch ----------------
extern "C" void kernel_launch(void* const* d_in, const int* in_sizes, int n_in,
                              void* d_out, int out_size) {
    const float* hs  = (const float*)d_in[0];
    const int*   msk = (const int*)  d_in[1];
    const float* Wq  = (const float*)d_in[2];
    const float* Wk  = (const float*)d_in[3];
    const float* Wv  = (const float*)d_in[4];
    const float* Wo  = (const float*)d_in[5];
    float* out = (float*)d_out;

    // split fp32 -> (hi, lo) bf16
    split_bf16<<<(1048576 + 255) / 256, 256>>>(hs, 0, 1048576);
    split_bf16<<<(262144  + 255) / 256, 256>>>(Wq, 1, 262144);
    split_bf16<<<(65536   + 255) / 256, 256>>>(Wk, 2, 65536);
    split_bf16<<<(65536   + 255) / 256, 256>>>(Wv, 3, 65536);
    split_bf16<<<(262144  + 255) / 256, 256>>>(Wo, 4, 262144);

    // QKV projection on HMMA (N = 1536)
    gemm_mma<<<dim3(1536 / BN, (BB * SS) / BM), 256>>>(0, nullptr);

    // RoPE -> fp16 Q (scaled) / K; V -> fp16 hi/lo
    int ropeThreads = (BB * HQ * SS + BB * HKV * SS) * 16;
    rope_f16<<<(ropeThreads + 255) / 256, 256>>>();
    vconv<<<(262144 + 255) / 256, 256>>>(262144);

    // causal GQA flash attention on HMMA
    attn_mma<<<dim3(SS / 32, HKV, BB), 256>>>(msk);

    // split attention output, then output projection on HMMA
    split_bf16<<<(1048576 + 255) / 256, 256>>>(nullptr, 5, 1048576);
    gemm_mma<<<dim3(DMODEL / BN, (BB * SS) / BM), 256>>>(1, out);
}

// round 17
// speedup vs baseline: 3.1031x; 1.1397x over previous
#include <cuda_runtime.h>
#include <cuda_bf16.h>
#include <cuda_fp16.h>
#include <math.h>
#include <stdint.h>

#define BB     2
#define SS     2048
#define DMODEL 1024
#define HQ     32
#define HKV    8
#define HD     32

// ---------------- scratch (no allocs allowed) ----------------
__device__ float g_q [BB*HQ *SS*HD];   // [b][h][s][d] fp32 (pre-rope)
__device__ float g_k [BB*HKV*SS*HD];
__device__ float g_v [BB*HKV*SS*HD];
__device__ float g_ao[BB*SS*DMODEL];   // attention out, [b][s][h*HD+d]

// fp16 attention operands
__device__ __align__(16) __half g_q16 [BB*HQ *SS*HD];  // roped, pre-scaled
__device__ __align__(16) __half g_k16 [BB*HKV*SS*HD];  // roped
__device__ __align__(16) __half g_vh16[BB*HKV*SS*HD];
__device__ __align__(16) __half g_vl16[BB*HKV*SS*HD];

// bf16 split-precision operands (hi/lo) for projections
__device__ __align__(16) __nv_bfloat16 g_hsh[BB*SS*DMODEL];
__device__ __align__(16) __nv_bfloat16 g_hsl[BB*SS*DMODEL];
__device__ __align__(16) __nv_bfloat16 g_wh [1536*DMODEL];
__device__ __align__(16) __nv_bfloat16 g_wl [1536*DMODEL];
__device__ __align__(16) __nv_bfloat16 g_woh[DMODEL*DMODEL];
__device__ __align__(16) __nv_bfloat16 g_wol[DMODEL*DMODEL];
__device__ __align__(16) __nv_bfloat16 g_aoh[BB*SS*DMODEL];
__device__ __align__(16) __nv_bfloat16 g_aol[BB*SS*DMODEL];

__device__ __forceinline__ uint32_t smem_u32(const void* p) {
    uint32_t a;
    asm("{ .reg .u64 t; cvta.to.shared.u64 t, %1; cvt.u32.u64 %0, t; }"
        : "=r"(a) : "l"(p));
    return a;
}
__device__ __forceinline__ void ldsm4(uint32_t& r0, uint32_t& r1,
                                      uint32_t& r2, uint32_t& r3, uint32_t addr) {
    asm volatile("ldmatrix.sync.aligned.m8n8.x4.shared.b16 {%0,%1,%2,%3}, [%4];"
                 : "=r"(r0), "=r"(r1), "=r"(r2), "=r"(r3) : "r"(addr));
}
__device__ __forceinline__ void ldsm4t(uint32_t& r0, uint32_t& r1,
                                       uint32_t& r2, uint32_t& r3, uint32_t addr) {
    asm volatile("ldmatrix.sync.aligned.m8n8.x4.trans.shared.b16 {%0,%1,%2,%3}, [%4];"
                 : "=r"(r0), "=r"(r1), "=r"(r2), "=r"(r3) : "r"(addr));
}
__device__ __forceinline__ void mma16816(float* c, const uint32_t* a, const uint32_t* b) {
    asm volatile(
        "mma.sync.aligned.m16n8k16.row.col.f32.bf16.bf16.f32 "
        "{%0,%1,%2,%3}, {%4,%5,%6,%7}, {%8,%9}, {%0,%1,%2,%3};"
        : "+f"(c[0]), "+f"(c[1]), "+f"(c[2]), "+f"(c[3])
        : "r"(a[0]), "r"(a[1]), "r"(a[2]), "r"(a[3]), "r"(b[0]), "r"(b[1]));
}
__device__ __forceinline__ void mma16816h(float* c, const uint32_t* a,
                                          uint32_t b0, uint32_t b1) {
    asm volatile(
        "mma.sync.aligned.m16n8k16.row.col.f32.f16.f16.f32 "
        "{%0,%1,%2,%3}, {%4,%5,%6,%7}, {%8,%9}, {%0,%1,%2,%3};"
        : "+f"(c[0]), "+f"(c[1]), "+f"(c[2]), "+f"(c[3])
        : "r"(a[0]), "r"(a[1]), "r"(a[2]), "r"(a[3]), "r"(b0), "r"(b1));
}
#define CPASYNC16(dst, src) \
    asm volatile("cp.async.cg.shared.global [%0], [%1], 16;" :: "r"(dst), "l"(src))
#define CP_COMMIT() asm volatile("cp.async.commit_group;" ::: "memory")
#define CP_WAIT0()  asm volatile("cp.async.wait_group 0;"  ::: "memory")

// ---------------- split fp32 -> (hi, lo) bf16 ----------------
__global__ void split_bf16(const float* __restrict__ src, int which, int n4) {
    int i = blockIdx.x * 256 + threadIdx.x;
    if (i >= n4) return;
    __nv_bfloat16 *ho, *lo;
    const float* s = src;
    switch (which) {
        case 0:  ho = g_hsh;              lo = g_hsl;              break;
        case 1:  ho = g_wh;               lo = g_wl;               break;
        case 2:  ho = g_wh + 1024*1024;   lo = g_wl + 1024*1024;   break;
        case 3:  ho = g_wh + 1280*1024;   lo = g_wl + 1280*1024;   break;
        case 4:  ho = g_woh;              lo = g_wol;              break;
        default: ho = g_aoh;              lo = g_aol; s = g_ao;    break;
    }
    float4 x = ((const float4*)s)[i];
    __nv_bfloat162 h01, h23, l01, l23;
    h01.x = __float2bfloat16(x.x); h01.y = __float2bfloat16(x.y);
    h23.x = __float2bfloat16(x.z); h23.y = __float2bfloat16(x.w);
    l01.x = __float2bfloat16(x.x - __bfloat162float(h01.x));
    l01.y = __float2bfloat16(x.y - __bfloat162float(h01.y));
    l23.x = __float2bfloat16(x.z - __bfloat162float(h23.x));
    l23.y = __float2bfloat16(x.w - __bfloat162float(h23.y));
    ((__nv_bfloat162*)ho)[2*i]   = h01;
    ((__nv_bfloat162*)ho)[2*i+1] = h23;
    ((__nv_bfloat162*)lo)[2*i]   = l01;
    ((__nv_bfloat162*)lo)[2*i+1] = l23;
}

// ---------------- fused 3-term HMMA GEMM, cp.async double-buffered ----------
// C[m,n] = sum_k A[m,k]*B[n,k] via Ah*Bh + Ah*Bl + Al*Bh per K-chunk.
#define BM 128
#define BN 128
#define CHK 32
#define NCH (DMODEL / CHK)        // 32
#define RSTB   80                 // row stride bytes (32 halves + 8 pad)
#define TILE_B (128 * RSTB)       // 10240 B per tile
#define STG_B  (4 * TILE_B)       // 40960 B per stage (Ah,Al,Bh,Bl)
#define SMEM_DYN (2 * STG_B)      // 81920 B

__global__ __launch_bounds__(256) void gemm_mma(int mode, float* __restrict__ Cout) {
    extern __shared__ __align__(16) char dyn[];
    const uint32_t sbase = smem_u32(dyn);

    const int tid    = threadIdx.x;
    const int lane   = tid & 31;
    const int wid    = tid >> 5;
    const int warp_m = wid & 1;
    const int warp_n = wid >> 1;
    const int m0     = blockIdx.y * BM;
    const int n0     = blockIdx.x * BN;

    const __nv_bfloat16* Ah = (mode == 0) ? g_hsh : g_aoh;
    const __nv_bfloat16* Al = (mode == 0) ? g_hsl : g_aol;
    const __nv_bfloat16* Bh = (mode == 0) ? g_wh  : g_woh;
    const __nv_bfloat16* Bl = (mode == 0) ? g_wl  : g_wol;

    float acc[4][4][4];
    #pragma unroll
    for (int mt = 0; mt < 4; mt++)
        #pragma unroll
        for (int nt = 0; nt < 4; nt++)
            #pragma unroll
            for (int c = 0; c < 4; c++) acc[mt][nt][c] = 0.f;

    // chunk copy: 4 tiles x 128 rows x 64B -> 8 cp.async(16B) per thread
    auto copy_chunk = [&](int g, int s) {
        const __nv_bfloat16* srcs[4] = {Ah, Al, Bh, Bl};
        const uint32_t dst0 = sbase + s * STG_B;
        #pragma unroll
        for (int i = 0; i < 8; i++) {
            int t    = tid + i * 256;
            int row  = t >> 2;
            int seg  = t & 3;
            int tile = row >> 7;          // compile-time per i
            int r    = row & 127;
            int base = (tile < 2) ? m0 : n0;
            const __nv_bfloat16* sp = srcs[tile] + (size_t)(base + r) * DMODEL
                                    + g * CHK + seg * 8;
            CPASYNC16(dst0 + tile * TILE_B + r * RSTB + seg * 16, sp);
        }
        CP_COMMIT();
    };

    copy_chunk(0, 0);
    for (int g = 0; g < NCH; g++) {
        CP_WAIT0();
        __syncthreads();                  // chunk g visible; compute g-1 done
        if (g + 1 < NCH) copy_chunk(g + 1, (g + 1) & 1);

        const uint32_t stg = sbase + (g & 1) * STG_B;
        #pragma unroll
        for (int ks = 0; ks < 2; ks++) {
            uint32_t ah[4][4], al[4][4], bh[4][2], bl[4][2];
            #pragma unroll
            for (int mt = 0; mt < 4; mt++) {
                int row = warp_m * 64 + mt * 16 + (lane & 15);
                int col = ks * 16 + (lane >> 4) * 8;
                uint32_t off = row * RSTB + col * 2;
                ldsm4(ah[mt][0], ah[mt][1], ah[mt][2], ah[mt][3], stg + off);
                ldsm4(al[mt][0], al[mt][1], al[mt][2], al[mt][3],
                      stg + TILE_B + off);
            }
            #pragma unroll
            for (int nt2 = 0; nt2 < 2; nt2++) {
                int nrow = warp_n * 32 + nt2 * 16 + (lane >> 4) * 8 + (lane & 7);
                int col  = ks * 16 + ((lane >> 3) & 1) * 8;
                uint32_t off = nrow * RSTB + col * 2;
                ldsm4(bh[2*nt2][0], bh[2*nt2][1], bh[2*nt2+1][0], bh[2*nt2+1][1],
                      stg + 2 * TILE_B + off);
                ldsm4(bl[2*nt2][0], bl[2*nt2][1], bl[2*nt2+1][0], bl[2*nt2+1][1],
                      stg + 3 * TILE_B + off);
            }
            #pragma unroll
            for (int mt = 0; mt < 4; mt++)
                #pragma unroll
                for (int nt = 0; nt < 4; nt++) {
                    mma16816(acc[mt][nt], ah[mt], bh[nt]);
                    mma16816(acc[mt][nt], ah[mt], bl[nt]);
                    mma16816(acc[mt][nt], al[mt], bh[nt]);
                }
        }
        __syncthreads();                  // all warps done with stage before reuse
    }

    const int gid = lane >> 2;
    const int tig = lane & 3;
    #pragma unroll
    for (int mt = 0; mt < 4; mt++) {
        int mrow = m0 + warp_m * 64 + mt * 16 + gid;
        #pragma unroll
        for (int nt = 0; nt < 4; nt++) {
            int nl = n0 + warp_n * 32 + nt * 8 + 2 * tig;
            #pragma unroll
            for (int half = 0; half < 2; half++) {
                int m = mrow + half * 8;
                float2 v = make_float2(acc[mt][nt][2*half], acc[mt][nt][2*half+1]);
                float* o;
                if (mode == 1) {
                    o = Cout + m * DMODEL + nl;
                } else {
                    int b = m >> 11, s = m & (SS - 1);
                    if (nl < 1024)
                        o = g_q + ((b * HQ + (nl >> 5)) * SS + s) * HD + (nl & 31);
                    else if (nl < 1280) {
                        int t = nl - 1024;
                        o = g_k + ((b * HKV + (t >> 5)) * SS + s) * HD + (t & 31);
                    } else {
                        int t = nl - 1280;
                        o = g_v + ((b * HKV + (t >> 5)) * SS + s) * HD + (t & 31);
                    }
                }
                *(float2*)o = v;
            }
        }
    }
}

// ---------------- RoPE fp32 -> fp16 (Q pre-scaled) ----------------
__global__ void rope_f16() {
    const int NQROWS = BB * HQ * SS;
    const int TOT    = (NQROWS + BB * HKV * SS) * 16;
    int gid = blockIdx.x * blockDim.x + threadIdx.x;
    if (gid >= TOT) return;
    int row = gid >> 4;
    int i   = gid & 15;
    const float* src;
    __half* dst;
    float postscale;
    if (row < NQROWS) {
        src = g_q + row * HD;  dst = g_q16 + row * HD;
        postscale = 0.17677669529663687f;   // 1/sqrt(32)
    } else {
        int kr = row - NQROWS;
        src = g_k + kr * HD;   dst = g_k16 + kr * HD;
        postscale = 1.0f;
    }
    int s = row & (SS - 1);
    float inv_freq = expf(-(float)i * (9.210340371976184f / 16.0f));
    float ang = (float)s * inv_freq;
    float c, sn;
    sincosf(ang, &sn, &c);
    float x1 = src[i];
    float x2 = src[i + 16];
    dst[i]      = __float2half((x1 * c - x2 * sn) * postscale);
    dst[i + 16] = __float2half((x2 * c + x1 * sn) * postscale);
}

// ---------------- V fp32 -> fp16 hi/lo ----------------
__global__ void vconv(int n4) {
    int i = blockIdx.x * 256 + threadIdx.x;
    if (i >= n4) return;
    float4 x = ((const float4*)g_v)[i];
    __half2 h01 = __floats2half2_rn(x.x, x.y);
    __half2 h23 = __floats2half2_rn(x.z, x.w);
    float2 f01 = __half22float2(h01);
    float2 f23 = __half22float2(h23);
    __half2 l01 = __floats2half2_rn(x.x - f01.x, x.y - f01.y);
    __half2 l23 = __floats2half2_rn(x.z - f23.x, x.w - f23.y);
    ((__half2*)g_vh16)[2*i]   = h01;
    ((__half2*)g_vh16)[2*i+1] = h23;
    ((__half2*)g_vl16)[2*i]   = l01;
    ((__half2*)g_vl16)[2*i+1] = l23;
}

// ---------------- HMMA causal GQA flash attention (unchanged) ----------------
#define VST 40

__global__ __launch_bounds__(256) void attn_mma(const int* __restrict__ mask) {
    __shared__ __align__(16) __half sK [64][VST];
    __shared__ __align__(16) __half sVh[64][VST];
    __shared__ __align__(16) __half sVl[64][VST];
    __shared__ int smask[64];

    const int tid  = threadIdx.x;
    const int lane = tid & 31;
    const int w    = tid >> 5;
    const int b    = blockIdx.z;
    const int kvh  = blockIdx.y;
    const int q0   = blockIdx.x * 32;
    const int h    = kvh * 4 + (w >> 1);
    const int g    = lane >> 2;
    const int tig  = lane & 3;
    const int R0   = q0 + (w & 1) * 16 + g;
    const int R1   = R0 + 8;

    const __half* Qb = g_q16 + (size_t)(b * HQ + h) * SS * HD;
    uint32_t aQ[2][4];
    #pragma unroll
    for (int ks = 0; ks < 2; ks++) {
        aQ[ks][0] = *(const uint32_t*)(Qb + R0 * HD + ks * 16 + 2 * tig);
        aQ[ks][1] = *(const uint32_t*)(Qb + R1 * HD + ks * 16 + 2 * tig);
        aQ[ks][2] = *(const uint32_t*)(Qb + R0 * HD + ks * 16 + 2 * tig + 8);
        aQ[ks][3] = *(const uint32_t*)(Qb + R1 * HD + ks * 16 + 2 * tig + 8);
    }

    const __half* Kg  = g_k16  + (size_t)(b * HKV + kvh) * SS * HD;
    const __half* Vhg = g_vh16 + (size_t)(b * HKV + kvh) * SS * HD;
    const __half* Vlg = g_vl16 + (size_t)(b * HKV + kvh) * SS * HD;
    const int*    mb  = mask + b * SS;

    float O[4][4];
    #pragma unroll
    for (int nt = 0; nt < 4; nt++)
        #pragma unroll
        for (int c = 0; c < 4; c++) O[nt][c] = 0.f;
    float m0 = -1e30f, m1 = -1e30f, l0 = 0.f, l1 = 0.f;

    const int lr = tid >> 2;
    const int lg = (tid & 3) * 8;

    for (int j0 = 0; j0 < q0 + 32; j0 += 64) {
        *(int4*)&sK [lr][lg] = *(const int4*)(Kg  + (j0 + lr) * HD + lg);
        *(int4*)&sVh[lr][lg] = *(const int4*)(Vhg + (j0 + lr) * HD + lg);
        *(int4*)&sVl[lr][lg] = *(const int4*)(Vlg + (j0 + lr) * HD + lg);
        if (tid < 64) smask[tid] = mb[j0 + tid];
        __syncthreads();

        float sf[8][4];
        #pragma unroll
        for (int nt = 0; nt < 8; nt++)
            #pragma unroll
            for (int c = 0; c < 4; c++) sf[nt][c] = 0.f;

        #pragma unroll
        for (int nt2 = 0; nt2 < 4; nt2++) {
            #pragma unroll
            for (int ks = 0; ks < 2; ks++) {
                uint32_t b0, b1, b2, b3;
                int nrow = nt2 * 16 + (lane >> 4) * 8 + (lane & 7);
                int col  = ks * 16 + ((lane >> 3) & 1) * 8;
                ldsm4(b0, b1, b2, b3, smem_u32(&sK[nrow][col]));
                mma16816h(sf[2*nt2],   aQ[ks], b0, b1);
                mma16816h(sf[2*nt2+1], aQ[ks], b2, b3);
            }
        }

        float tm0 = -1e30f, tm1 = -1e30f;
        #pragma unroll
        for (int nt = 0; nt < 8; nt++) {
            int cb = nt * 8 + 2 * tig;
            #pragma unroll
            for (int cc = 0; cc < 2; cc++) {
                int cg = j0 + cb + cc;
                bool mk = smask[cb + cc] != 0;
                sf[nt][cc]     = (cg <= R0 && mk) ? sf[nt][cc]     : -1e9f;
                sf[nt][2 + cc] = (cg <= R1 && mk) ? sf[nt][2 + cc] : -1e9f;
                tm0 = fmaxf(tm0, sf[nt][cc]);
                tm1 = fmaxf(tm1, sf[nt][2 + cc]);
            }
        }
        tm0 = fmaxf(tm0, __shfl_xor_sync(0xFFFFFFFFu, tm0, 1));
        tm0 = fmaxf(tm0, __shfl_xor_sync(0xFFFFFFFFu, tm0, 2));
        tm1 = fmaxf(tm1, __shfl_xor_sync(0xFFFFFFFFu, tm1, 1));
        tm1 = fmaxf(tm1, __shfl_xor_sync(0xFFFFFFFFu, tm1, 2));

        if (tm0 > m0) {
            float cr = __expf(m0 - tm0);
            l0 *= cr;
            #pragma unroll
            for (int nt = 0; nt < 4; nt++) { O[nt][0] *= cr; O[nt][1] *= cr; }
            m0 = tm0;
        }
        if (tm1 > m1) {
            float cr = __expf(m1 - tm1);
            l1 *= cr;
            #pragma unroll
            for (int nt = 0; nt < 4; nt++) { O[nt][2] *= cr; O[nt][3] *= cr; }
            m1 = tm1;
        }

        float ls0 = 0.f, ls1 = 0.f;
        uint32_t aPh[4][4], aPl[4][4];
        #pragma unroll
        for (int nt = 0; nt < 8; nt++) {
            float p0 = __expf(sf[nt][0] - m0);
            float p1 = __expf(sf[nt][1] - m0);
            float p2 = __expf(sf[nt][2] - m1);
            float p3 = __expf(sf[nt][3] - m1);
            ls0 += p0 + p1;
            ls1 += p2 + p3;
            __half2 h01 = __floats2half2_rn(p0, p1);
            __half2 h23 = __floats2half2_rn(p2, p3);
            float2 f01 = __half22float2(h01);
            float2 f23 = __half22float2(h23);
            __half2 e01 = __floats2half2_rn(p0 - f01.x, p1 - f01.y);
            __half2 e23 = __floats2half2_rn(p2 - f23.x, p3 - f23.y);
            int kf = nt >> 1, pt = (nt & 1) * 2;
            aPh[kf][pt]     = *(uint32_t*)&h01;
            aPh[kf][pt + 1] = *(uint32_t*)&h23;
            aPl[kf][pt]     = *(uint32_t*)&e01;
            aPl[kf][pt + 1] = *(uint32_t*)&e23;
        }
        ls0 += __shfl_xor_sync(0xFFFFFFFFu, ls0, 1);
        ls0 += __shfl_xor_sync(0xFFFFFFFFu, ls0, 2);
        ls1 += __shfl_xor_sync(0xFFFFFFFFu, ls1, 1);
        ls1 += __shfl_xor_sync(0xFFFFFFFFu, ls1, 2);
        l0 += ls0;
        l1 += ls1;

        const int vr = (lane & 7) + ((lane >> 3) & 1) * 8;
        const int vc = ((lane >> 4) & 1) * 8;
        #pragma unroll
        for (int kf = 0; kf < 4; kf++) {
            int kr = kf * 16 + vr;
            uint32_t v0, v1, v2, v3;
            ldsm4t(v0, v1, v2, v3, smem_u32(&sVh[kr][vc]));
            mma16816h(O[0], aPh[kf], v0, v1);
            mma16816h(O[1], aPh[kf], v2, v3);
            mma16816h(O[0], aPl[kf], v0, v1);
            mma16816h(O[1], aPl[kf], v2, v3);
            ldsm4t(v0, v1, v2, v3, smem_u32(&sVh[kr][16 + vc]));
            mma16816h(O[2], aPh[kf], v0, v1);
            mma16816h(O[3], aPh[kf], v2, v3);
            mma16816h(O[2], aPl[kf], v0, v1);
            mma16816h(O[3], aPl[kf], v2, v3);
            ldsm4t(v0, v1, v2, v3, smem_u32(&sVl[kr][vc]));
            mma16816h(O[0], aPh[kf], v0, v1);
            mma16816h(O[1], aPh[kf], v2, v3);
            ldsm4t(v0, v1, v2, v3, smem_u32(&sVl[kr][16 + vc]));
            mma16816h(O[2], aPh[kf], v0, v1);
            mma16816h(O[3], aPh[kf], v2, v3);
        }
        __syncthreads();
    }

    float i0 = 1.0f / l0;
    float i1 = 1.0f / l1;
    float* o0 = g_ao + (size_t)(b * SS + R0) * DMODEL + h * HD + 2 * tig;
    float* o1 = g_ao + (size_t)(b * SS + R1) * DMODEL + h * HD + 2 * tig;
    #pragma unroll
    for (int nt = 0; nt < 4; nt++) {
        *(float2*)(o0 + nt * 8) = make_float2(O[nt][0] * i0, O[nt][1] * i0);
        *(float2*)(o1 + nt * 8) = make_float2(O[nt][2] * i1, O[nt][3] * i1);
    }
}

// ---------------- launch ----------------
extern "C" void kernel_launch(void* const* d_in, const int* in_sizes, int n_in,
                              void* d_out, int out_size) {
    const float* hs  = (const float*)d_in[0];
    const int*   msk = (const int*)  d_in[1];
    const float* Wq  = (const float*)d_in[2];
    const float* Wk  = (const float*)d_in[3];
    const float* Wv  = (const float*)d_in[4];
    const float* Wo  = (const float*)d_in[5];
    float* out = (float*)d_out;

    cudaFuncSetAttribute(gemm_mma, cudaFuncAttributeMaxDynamicSharedMemorySize,
                         SMEM_DYN);

    // split fp32 -> (hi, lo) bf16
    split_bf16<<<(1048576 + 255) / 256, 256>>>(hs, 0, 1048576);
    split_bf16<<<(262144  + 255) / 256, 256>>>(Wq, 1, 262144);
    split_bf16<<<(65536   + 255) / 256, 256>>>(Wk, 2, 65536);
    split_bf16<<<(65536   + 255) / 256, 256>>>(Wv, 3, 65536);
    split_bf16<<<(262144  + 255) / 256, 256>>>(Wo, 4, 262144);

    // QKV projection on HMMA (N = 1536)
    gemm_mma<<<dim3(1536 / BN, (BB * SS) / BM), 256, SMEM_DYN>>>(0, nullptr);

    // RoPE -> fp16 Q (scaled) / K; V -> fp16 hi/lo
    int ropeThreads = (BB * HQ * SS + BB * HKV * SS) * 16;
    rope_f16<<<(ropeThreads + 255) / 256, 256>>>();
    vconv<<<(262144 + 255) / 256, 256>>>(262144);

    // causal GQA flash attention on HMMA
    attn_mma<<<dim3(SS / 32, HKV, BB), 256>>>(msk);

    // split attention output, then output projection on HMMA
    split_bf16<<<(1048576 + 255) / 256, 256>>>(nullptr, 5, 1048576);
    gemm_mma<<<dim3(DMODEL / BN, (BB * SS) / BM), 256, SMEM_DYN>>>(1, out);
}